// round 14
// baseline (speedup 1.0000x reference)
#include <cuda_runtime.h>
#include <math.h>

// Problem constants
#define BB 2048   // batch
#define DD 512    // hidden
#define CC 128    // vocab
#define TT 151    // steps
#define G3 1536   // 3*DD

// Persistent scratch (allowed: __device__ globals, no runtime allocation)
__device__ float g_h[2][BB * DD];             // ping-pong hidden state, 8 MB
__device__ float g_tab[(CC + 1) * G3];        // gi table: embed@W_ih^T + b_ih (+ b_hh r/z folded)
__device__ int   g_tok[BB];                   // previous token per batch row
__device__ float g_log[(size_t)BB * TT * CC]; // logits staged [B,T,C] (coalesced), 158 MB
__device__ float g_part[16 * BB * CC];        // projection partials [n_tile][B][C], 16 MB
__device__ float g_wpt[DD * CC];              // W_proj transposed [D][C], 256 KB
__device__ int   g_done[64];                  // per-32-row m-block step flag

__device__ __forceinline__ float sigm(float x) { return 1.f / (1.f + expf(-x)); }

// Packed fp32x2 FMA (Blackwell FFMA2; only reachable via PTX fma.rn.f32x2)
#define FMA2(acc, a, b) \
    asm("fma.rn.f32x2 %0, %1, %2, %0;" : "+l"(acc) : "l"(a), "l"(b))

__device__ __forceinline__ float lo32(unsigned long long v) { return __uint_as_float((unsigned)v); }
__device__ __forceinline__ float hi32(unsigned long long v) { return __uint_as_float((unsigned)(v >> 32)); }

// duplicate one fp32 into both lanes of a packed f32x2 (ALU pipe, not LDS)
__device__ __forceinline__ unsigned long long dup2(float x) {
    unsigned long long r;
    asm("mov.b64 %0, {%1, %1};" : "=l"(r) : "f"(x));
    return r;
}

// ---------------------------------------------------------------------------
// Precompute gi table: g_tab[c][j] = embed[c]·W_ih[j] + b_ih[j] + (j<1024 ? b_hh[j] : 0)
// Row CC (=128) is the zero-input row (t=0): just the biases.
// ---------------------------------------------------------------------------
__global__ void build_tab(const float* __restrict__ Wih, const float* __restrict__ bih,
                          const float* __restrict__ bhh, const float* __restrict__ embed) {
    __shared__ float se[DD];
    int c = blockIdx.x;                      // 0..128
    int j = blockIdx.y * 256 + threadIdx.x;  // 0..1535
    for (int i = threadIdx.x; i < DD; i += 256)
        se[i] = (c < CC) ? embed[c * DD + i] : 0.f;
    __syncthreads();
    float acc = bih[j] + (j < 2 * DD ? bhh[j] : 0.f);
    if (c < CC) {
        const float4* w  = (const float4*)(Wih + (size_t)j * DD);
        const float4* s4 = (const float4*)se;
        #pragma unroll 8
        for (int k = 0; k < DD / 4; k++) {
            float4 wv = w[k], sv = s4[k];
            acc += wv.x * sv.x;
            acc += wv.y * sv.y;
            acc += wv.z * sv.z;
            acc += wv.w * sv.w;
        }
    }
    g_tab[(size_t)c * G3 + j] = acc;
}

// W_proj^T: g_wpt[n][c] = Wp[c][n]  (one-time, coalesced writes)
__global__ void build_wpt(const float* __restrict__ Wp) {
    int i = blockIdx.x * 256 + threadIdx.x;  // 0 .. 512*128-1
    int n = i >> 7, c = i & 127;
    g_wpt[n * CC + c] = Wp[(size_t)c * DD + n];
}

__global__ void init_tok() {
    int i = blockIdx.x * blockDim.x + threadIdx.x;
    if (i < BB) g_tok[i] = CC;  // zero-input table row
    if (i < 64) g_done[i] = 0;  // reset inline-finalize flags (every graph replay)
}

// ---------------------------------------------------------------------------
// Kernel 1: fine-grained tiles. Tile = 32 batch rows x 32 hidden cols x 3
// gates, K = full 512 (ascending, per-element sum bitwise-identical to R13).
// grid = 1024 CTAs x 64 threads, occ 8 -> ~6.9 tiles/SM, 1.2% imbalance.
//   bid 0..63    -> (mi=bid,  ni=0)  : these CTAs first finalize step t-1 for
//                                      their 32 rows (reduce 16 partials ->
//                                      logits/argmax/token), set g_done[mi].
//   bid 64..1023 -> (mi, ni=1..15)
// All CTAs poll g_done[mi] only at epilogue time (set ~tens of us earlier).
// Epilogue: gates -> h_new (global + smem), then 32-col projection partial.
// ---------------------------------------------------------------------------
__global__ __launch_bounds__(64, 8)
void step_h(const float* __restrict__ feat, const float* __restrict__ Whh,
            const float* __restrict__ bhh, const float* __restrict__ bp,
            float* __restrict__ out, int t) {
    // Smem: GEMM phase As[2][16][36] + Bs[2][3][16][36] floats (18432 B).
    //       Proj phase Hs[32][36] overlays As.
    __shared__ __align__(16) unsigned char sraw[18432];
    float (*As)[16][36]    = (float(*)[16][36])sraw;
    float (*Bs)[3][16][36] = (float(*)[3][16][36])(sraw + 2 * 16 * 36 * 4);
    float* Hs = (float*)sraw;  // stride 36

    const int bid = blockIdx.x;
    int mi, ni;
    if (bid < 64) { mi = bid; ni = 0; }
    else { int r = bid - 64; mi = r / 15; ni = 1 + r % 15; }
    const int m0 = mi * 32, n0 = ni * 32;

    const float* hin  = (t == 0) ? feat : g_h[(t - 1) & 1];
    float*       hout = g_h[t & 1];

    const int tid = threadIdx.x;
    const int ty = tid >> 3, tx = tid & 7;   // compute: m = ty*4+i, n = tx*4+j
    const int w = tid >> 5, lane = tid & 31; // warp layout for finalize/proj

    // ---- Inline finalize of step t-1 (ni==0 CTAs; bids 0..63 -> wave 1) ---
    if (t > 0 && ni == 0) {
        float* out_tok = out + (size_t)BB * CC * TT;
        const float4 bpv = *(const float4*)&bp[lane * 4];
        for (int rr = 0; rr < 16; rr++) {
            const int b = m0 + w * 16 + rr;
            float4 s = make_float4(0.f, 0.f, 0.f, 0.f);
            #pragma unroll
            for (int p = 0; p < 16; p++) {
                float4 v = *(const float4*)&g_part[((size_t)p * BB + b) * CC + lane * 4];
                s.x += v.x; s.y += v.y; s.z += v.z; s.w += v.w;
            }
            s.x += bpv.x; s.y += bpv.y; s.z += bpv.z; s.w += bpv.w;

            *(float4*)&g_log[((size_t)b * TT + (t - 1)) * CC + lane * 4] = s;

            // argmax, first-max semantics
            float vv[4] = {s.x, s.y, s.z, s.w};
            float bv = -3.402823466e38f;
            int bi = 0;
            #pragma unroll
            for (int j = 0; j < 4; j++) {
                if (vv[j] > bv) { bv = vv[j]; bi = lane * 4 + j; }
            }
            #pragma unroll
            for (int off = 16; off; off >>= 1) {
                float ov = __shfl_xor_sync(0xffffffffu, bv, off);
                int   oi = __shfl_xor_sync(0xffffffffu, bi, off);
                if (ov > bv || (ov == bv && oi < bi)) { bv = ov; bi = oi; }
            }
            if (lane == 0) {
                g_tok[b] = bi;
                out_tok[(size_t)b * TT + (t - 1)] = (float)bi;
            }
        }
        __threadfence();
        __syncthreads();
        if (tid == 0) atomicExch(&g_done[mi], t);
    }

    // ---- gh GEMM: per-element ascending K sum, bitwise-identical to R13 ---
    // Staging: A panel 32m x 16k (2 float4/thread), B panel 3g x 32n x 16k
    // (6 float4/thread). Scalar STS transpose into [k][m] / [g][k][n].
    const int rq = tid >> 2, kq = tid & 3;   // staging row 0..15, k-quad 0..3
    const float* paA = hin + (size_t)(m0 + rq) * DD + kq * 4;          // +16 rows for it1
    const float* paB = Whh + (size_t)(n0 + rq) * DD + kq * 4;          // base gate 0
    const size_t GSTRIDE = (size_t)DD * DD;                            // gate stride
    const size_t RSTRIDE = (size_t)16 * DD;                            // +16 rows

    unsigned long long acc[3][4][2];
    #pragma unroll
    for (int g = 0; g < 3; g++)
        #pragma unroll
        for (int i = 0; i < 4; i++) { acc[g][i][0] = 0ull; acc[g][i][1] = 0ull; }

    float4 av0, av1, bvv[6];

    #define LOAD_PANEL(kk)                                                 \
        do {                                                               \
            av0    = *(const float4*)(paA + (kk));                         \
            av1    = *(const float4*)(paA + RSTRIDE + (kk));               \
            bvv[0] = *(const float4*)(paB + (kk));                         \
            bvv[1] = *(const float4*)(paB + RSTRIDE + (kk));               \
            bvv[2] = *(const float4*)(paB + GSTRIDE + (kk));               \
            bvv[3] = *(const float4*)(paB + GSTRIDE + RSTRIDE + (kk));     \
            bvv[4] = *(const float4*)(paB + 2 * GSTRIDE + (kk));           \
            bvv[5] = *(const float4*)(paB + 2 * GSTRIDE + RSTRIDE + (kk)); \
        } while (0)

    #define STORE_PANEL(s)                                                      \
        do {                                                                    \
            As[s][kq * 4 + 0][rq] = av0.x; As[s][kq * 4 + 1][rq] = av0.y;       \
            As[s][kq * 4 + 2][rq] = av0.z; As[s][kq * 4 + 3][rq] = av0.w;       \
            As[s][kq * 4 + 0][rq + 16] = av1.x; As[s][kq * 4 + 1][rq + 16] = av1.y; \
            As[s][kq * 4 + 2][rq + 16] = av1.z; As[s][kq * 4 + 3][rq + 16] = av1.w; \
            Bs[s][0][kq * 4 + 0][rq] = bvv[0].x; Bs[s][0][kq * 4 + 1][rq] = bvv[0].y; \
            Bs[s][0][kq * 4 + 2][rq] = bvv[0].z; Bs[s][0][kq * 4 + 3][rq] = bvv[0].w; \
            Bs[s][0][kq * 4 + 0][rq + 16] = bvv[1].x; Bs[s][0][kq * 4 + 1][rq + 16] = bvv[1].y; \
            Bs[s][0][kq * 4 + 2][rq + 16] = bvv[1].z; Bs[s][0][kq * 4 + 3][rq + 16] = bvv[1].w; \
            Bs[s][1][kq * 4 + 0][rq] = bvv[2].x; Bs[s][1][kq * 4 + 1][rq] = bvv[2].y; \
            Bs[s][1][kq * 4 + 2][rq] = bvv[2].z; Bs[s][1][kq * 4 + 3][rq] = bvv[2].w; \
            Bs[s][1][kq * 4 + 0][rq + 16] = bvv[3].x; Bs[s][1][kq * 4 + 1][rq + 16] = bvv[3].y; \
            Bs[s][1][kq * 4 + 2][rq + 16] = bvv[3].z; Bs[s][1][kq * 4 + 3][rq + 16] = bvv[3].w; \
            Bs[s][2][kq * 4 + 0][rq] = bvv[4].x; Bs[s][2][kq * 4 + 1][rq] = bvv[4].y; \
            Bs[s][2][kq * 4 + 2][rq] = bvv[4].z; Bs[s][2][kq * 4 + 3][rq] = bvv[4].w; \
            Bs[s][2][kq * 4 + 0][rq + 16] = bvv[5].x; Bs[s][2][kq * 4 + 1][rq + 16] = bvv[5].y; \
            Bs[s][2][kq * 4 + 2][rq + 16] = bvv[5].z; Bs[s][2][kq * 4 + 3][rq + 16] = bvv[5].w; \
        } while (0)

    // Prologue: panel 0 -> buf 0; panel 1 into regs.
    LOAD_PANEL(0);
    STORE_PANEL(0);
    LOAD_PANEL(16);
    __syncthreads();

    for (int p = 0; p < 32; p++) {
        const int s = p & 1;
        if (p < 31)
            STORE_PANEL(s ^ 1);
        if (p < 30)
            LOAD_PANEL((p + 2) * 16);
        #pragma unroll
        for (int k = 0; k < 16; k++) {
            float4 a4 = *(const float4*)&As[s][k][ty * 4];
            ulonglong2 br = *(const ulonglong2*)&Bs[s][0][k][tx * 4];
            ulonglong2 bz = *(const ulonglong2*)&Bs[s][1][k][tx * 4];
            ulonglong2 bn = *(const ulonglong2*)&Bs[s][2][k][tx * 4];
            unsigned long long a[4] = {dup2(a4.x), dup2(a4.y), dup2(a4.z), dup2(a4.w)};
            #pragma unroll
            for (int i = 0; i < 4; i++) {
                FMA2(acc[0][i][0], a[i], br.x); FMA2(acc[0][i][1], a[i], br.y);
                FMA2(acc[1][i][0], a[i], bz.x); FMA2(acc[1][i][1], a[i], bz.y);
                FMA2(acc[2][i][0], a[i], bn.x); FMA2(acc[2][i][1], a[i], bn.y);
            }
        }
        __syncthreads();
    }
    #undef LOAD_PANEL
    #undef STORE_PANEL

    // ---- Wait for this m-block's tokens (set long ago by the ni==0 CTA) ---
    if (t > 0) {
        if (tid == 0) {
            while (((volatile int*)g_done)[mi] < t) { }
        }
        __syncthreads();
        __threadfence();  // acquire: order g_tok reads after flag observation
    }

    // Gate epilogue: gi from table (b_ih + b_hh r/z folded in), b_hh_n added.
    // Write h_new to global AND to Hs (smem) for the fused projection partial.
    const float4 bhn4 = *(const float4*)&bhh[2 * DD + n0 + tx * 4];
    #pragma unroll
    for (int i = 0; i < 4; i++) {
        int m = m0 + ty * 4 + i;
        int tok = g_tok[m];
        const float* tab = g_tab + (size_t)tok * G3 + n0 + tx * 4;
        float4 gir  = *(const float4*)(tab);
        float4 giz  = *(const float4*)(tab + DD);
        float4 gin  = *(const float4*)(tab + 2 * DD);
        float4 hold = *(const float4*)&hin[(size_t)m * DD + n0 + tx * 4];

        float gr[4], gz[4], gn[4];
        gr[0] = lo32(acc[0][i][0]); gr[1] = hi32(acc[0][i][0]);
        gr[2] = lo32(acc[0][i][1]); gr[3] = hi32(acc[0][i][1]);
        gz[0] = lo32(acc[1][i][0]); gz[1] = hi32(acc[1][i][0]);
        gz[2] = lo32(acc[1][i][1]); gz[3] = hi32(acc[1][i][1]);
        gn[0] = lo32(acc[2][i][0]); gn[1] = hi32(acc[2][i][0]);
        gn[2] = lo32(acc[2][i][1]); gn[3] = hi32(acc[2][i][1]);

        float ir[4] = {gir.x, gir.y, gir.z, gir.w};
        float iz[4] = {giz.x, giz.y, giz.z, giz.w};
        float in_[4] = {gin.x, gin.y, gin.z, gin.w};
        float bn_[4] = {bhn4.x, bhn4.y, bhn4.z, bhn4.w};
        float ho[4] = {hold.x, hold.y, hold.z, hold.w};
        float o[4];
        #pragma unroll
        for (int j = 0; j < 4; j++) {
            float r = sigm(ir[j] + gr[j]);
            float z = sigm(iz[j] + gz[j]);
            float n = tanhf(in_[j] + r * (gn[j] + bn_[j]));
            o[j] = (1.f - z) * n + z * ho[j];
            Hs[(ty * 4 + i) * 36 + tx * 4 + j] = o[j];
        }
        *(float4*)&hout[(size_t)m * DD + n0 + tx * 4] =
            make_float4(o[0], o[1], o[2], o[3]);
    }
    __syncthreads();

    // Projection partial: P[m][c] = sum_{k=0..31} Hs[m][k] * WpT[n0+k][c]
    // Warp w owns rows w*16..w*16+15 in 4 passes of 4; lane owns 4 classes.
    #pragma unroll
    for (int pass = 0; pass < 4; pass++) {
        float4 pacc[4];
        #pragma unroll
        for (int rr = 0; rr < 4; rr++) pacc[rr] = make_float4(0.f, 0.f, 0.f, 0.f);
        #pragma unroll
        for (int kq2 = 0; kq2 < 8; kq2++) {
            const float* wr = g_wpt + (size_t)(n0 + kq2 * 4) * CC + lane * 4;
            float4 w0 = *(const float4*)(wr);
            float4 w1 = *(const float4*)(wr + CC);
            float4 w2 = *(const float4*)(wr + 2 * CC);
            float4 w3 = *(const float4*)(wr + 3 * CC);
            #pragma unroll
            for (int rr = 0; rr < 4; rr++) {
                float4 a4 = *(const float4*)&Hs[(w * 16 + pass * 4 + rr) * 36 + kq2 * 4];
                pacc[rr].x += a4.x * w0.x; pacc[rr].y += a4.x * w0.y;
                pacc[rr].z += a4.x * w0.z; pacc[rr].w += a4.x * w0.w;
                pacc[rr].x += a4.y * w1.x; pacc[rr].y += a4.y * w1.y;
                pacc[rr].z += a4.y * w1.z; pacc[rr].w += a4.y * w1.w;
                pacc[rr].x += a4.z * w2.x; pacc[rr].y += a4.z * w2.y;
                pacc[rr].z += a4.z * w2.z; pacc[rr].w += a4.z * w2.w;
                pacc[rr].x += a4.w * w3.x; pacc[rr].y += a4.w * w3.y;
                pacc[rr].z += a4.w * w3.z; pacc[rr].w += a4.w * w3.w;
            }
        }
        #pragma unroll
        for (int rr = 0; rr < 4; rr++) {
            int b = m0 + w * 16 + pass * 4 + rr;
            *(float4*)&g_part[((size_t)ni * BB + b) * CC + lane * 4] = pacc[rr];
        }
    }
}

// ---------------------------------------------------------------------------
// Kernel 2 (once, after the loop): finalize step TT-1 (16 partials).
// grid 256 CTAs x 256 threads; one warp per batch row.
// ---------------------------------------------------------------------------
__global__ __launch_bounds__(256)
void finalize(const float* __restrict__ bp, float* __restrict__ out, int t) {
    const int tid = threadIdx.x;
    const int w = tid >> 5, lane = tid & 31;
    const int b = blockIdx.x * 8 + w;

    float4 s = make_float4(0.f, 0.f, 0.f, 0.f);
    #pragma unroll
    for (int p = 0; p < 16; p++) {
        float4 v = *(const float4*)&g_part[((size_t)p * BB + b) * CC + lane * 4];
        s.x += v.x; s.y += v.y; s.z += v.z; s.w += v.w;
    }
    const float4 bpv = *(const float4*)&bp[lane * 4];
    s.x += bpv.x; s.y += bpv.y; s.z += bpv.z; s.w += bpv.w;

    *(float4*)&g_log[((size_t)b * TT + t) * CC + lane * 4] = s;

    // argmax, first-max semantics
    float vv[4] = {s.x, s.y, s.z, s.w};
    float bv = -3.402823466e38f;
    int bi = 0;
    #pragma unroll
    for (int j = 0; j < 4; j++) {
        if (vv[j] > bv) { bv = vv[j]; bi = lane * 4 + j; }
    }
    #pragma unroll
    for (int off = 16; off; off >>= 1) {
        float ov = __shfl_xor_sync(0xffffffffu, bv, off);
        int   oi = __shfl_xor_sync(0xffffffffu, bi, off);
        if (ov > bv || (ov == bv && oi < bi)) { bv = ov; bi = oi; }
    }
    if (lane == 0) {
        g_tok[b] = bi;
        float* out_tok = out + (size_t)BB * CC * TT;
        out_tok[(size_t)b * TT + t] = (float)bi;
    }
}

// ---------------------------------------------------------------------------
// Kernel 3 (once, at end): transpose staged logits [B,T,C] -> d_out [B,C,T].
// ---------------------------------------------------------------------------
__global__ __launch_bounds__(256)
void transp(float* __restrict__ out) {
    __shared__ float tile[32][33];
    const int b  = blockIdx.z;
    const int t0 = blockIdx.x * 32, c0 = blockIdx.y * 32;
    const int tx = threadIdx.x, ty = threadIdx.y;

    #pragma unroll
    for (int i = ty; i < 32; i += 8) {
        int t = t0 + i;
        if (t < TT)
            tile[i][tx] = g_log[((size_t)b * TT + t) * CC + c0 + tx];
    }
    __syncthreads();
    #pragma unroll
    for (int i = ty; i < 32; i += 8) {
        int c = c0 + i;
        int t = t0 + tx;
        if (t < TT)
            out[((size_t)b * CC + c) * TT + t] = tile[tx][i];
    }
}

// ---------------------------------------------------------------------------
// kernel_launch: graph-capturable, no allocation.
// Inputs (metadata order): feat, W_ih, W_hh, b_ih, b_hh, W_proj, b_proj, embed
// Output: logits [B,C,T] float32 then tokens [B,T] as float32.
// ---------------------------------------------------------------------------
extern "C" void kernel_launch(void* const* d_in, const int* in_sizes, int n_in,
                              void* d_out, int out_size) {
    const float* feat  = (const float*)d_in[0];
    const float* Wih   = (const float*)d_in[1];
    const float* Whh   = (const float*)d_in[2];
    const float* bih   = (const float*)d_in[3];
    const float* bhh   = (const float*)d_in[4];
    const float* Wp    = (const float*)d_in[5];
    const float* bp    = (const float*)d_in[6];
    const float* embed = (const float*)d_in[7];
    float* out = (float*)d_out;

    build_tab<<<dim3(CC + 1, G3 / 256), 256>>>(Wih, bih, bhh, embed);
    build_wpt<<<DD * CC / 256, 256>>>(Wp);
    init_tok<<<(BB + 255) / 256, 256>>>();

    for (int t = 0; t < TT; t++) {
        step_h<<<1024, 64>>>(feat, Whh, bhh, bp, out, t);
    }
    finalize<<<BB / 8, 256>>>(bp, out, TT - 1);

    transp<<<dim3((TT + 31) / 32, CC / 32, BB), dim3(32, 8)>>>(out);
}

// round 16
// speedup vs baseline: 1.1941x; 1.1941x over previous
#include <cuda_runtime.h>
#include <math.h>

// Problem constants
#define BB 2048   // batch
#define DD 512    // hidden
#define CC 128    // vocab
#define TT 151    // steps
#define G3 1536   // 3*DD

// Persistent scratch (allowed: __device__ globals, no runtime allocation)
__device__ float g_h[2][BB * DD];             // ping-pong hidden state, 8 MB
__device__ float g_tab[(CC + 1) * G3];        // gi table: embed@W_ih^T + b_ih (+ b_hh r/z folded)
__device__ int   g_tok[BB];                   // previous token per batch row
__device__ float g_log[(size_t)BB * TT * CC]; // logits staged [B,T,C] (coalesced), 158 MB
__device__ float g_part[8 * BB * CC];         // projection partials [n_tile][B][C], 8 MB
__device__ float g_wpt[DD * CC];              // W_proj transposed [D][C], 256 KB
__device__ int   g_done[32];                  // per-m-block step flag for inline finalize

__device__ __forceinline__ float sigm(float x) { return 1.f / (1.f + expf(-x)); }

// Packed fp32x2 FMA (Blackwell FFMA2; only reachable via PTX fma.rn.f32x2)
#define FMA2(acc, a, b) \
    asm("fma.rn.f32x2 %0, %1, %2, %0;" : "+l"(acc) : "l"(a), "l"(b))

__device__ __forceinline__ float lo32(unsigned long long v) { return __uint_as_float((unsigned)v); }
__device__ __forceinline__ float hi32(unsigned long long v) { return __uint_as_float((unsigned)(v >> 32)); }

// duplicate one fp32 into both lanes of a packed f32x2 (ALU pipe, not LDS)
__device__ __forceinline__ unsigned long long dup2(float x) {
    unsigned long long r;
    asm("mov.b64 %0, {%1, %1};" : "=l"(r) : "f"(x));
    return r;
}

// ---------------------------------------------------------------------------
// Precompute gi table: g_tab[c][j] = embed[c]·W_ih[j] + b_ih[j] + (j<1024 ? b_hh[j] : 0)
// Row CC (=128) is the zero-input row (t=0): just the biases.
// ---------------------------------------------------------------------------
__global__ void build_tab(const float* __restrict__ Wih, const float* __restrict__ bih,
                          const float* __restrict__ bhh, const float* __restrict__ embed) {
    __shared__ float se[DD];
    int c = blockIdx.x;                      // 0..128
    int j = blockIdx.y * 256 + threadIdx.x;  // 0..1535
    for (int i = threadIdx.x; i < DD; i += 256)
        se[i] = (c < CC) ? embed[c * DD + i] : 0.f;
    __syncthreads();
    float acc = bih[j] + (j < 2 * DD ? bhh[j] : 0.f);
    if (c < CC) {
        const float4* w  = (const float4*)(Wih + (size_t)j * DD);
        const float4* s4 = (const float4*)se;
        #pragma unroll 8
        for (int k = 0; k < DD / 4; k++) {
            float4 wv = w[k], sv = s4[k];
            acc += wv.x * sv.x;
            acc += wv.y * sv.y;
            acc += wv.z * sv.z;
            acc += wv.w * sv.w;
        }
    }
    g_tab[(size_t)c * G3 + j] = acc;
}

// W_proj^T: g_wpt[n][c] = Wp[c][n]  (one-time, coalesced writes)
__global__ void build_wpt(const float* __restrict__ Wp) {
    int i = blockIdx.x * 256 + threadIdx.x;  // 0 .. 512*128-1
    int n = i >> 7, c = i & 127;
    g_wpt[n * CC + c] = Wp[(size_t)c * DD + n];
}

__global__ void init_tok() {
    int i = blockIdx.x * blockDim.x + threadIdx.x;
    if (i < BB) g_tok[i] = CC;  // zero-input table row
    if (i < 32) g_done[i] = 0;  // reset inline-finalize flags (every graph replay)
}

// ---------------------------------------------------------------------------
// Kernel 1: (a) CTAs with blockIdx.y==0 first finalize step t-1 for their own
//           64 batch rows (reduce 8 projection partials + bias -> logits
//           staged [B,T,C], argmax -> g_tok, token output), then set flag.
//           (b) gh = h @ W_hh^T (FFMA2 GEMM; per-element accumulation
//           bitwise-identical to R13 — only the thread->tile index map is
//           swapped so the 3-gate B operand gets the warp broadcast dedup:
//           m <- tid&15 (A streamed, 16 distinct/warp), n <- tid>>4
//           (B broadcast, 2 distinct/warp). Crossbar: 800 -> 352 B/warp-k.
//           (c) gates + gi table lookup -> h_new, then this CTA's 64-col
//           partial of the projection h_new @ Wp^T.
// grid (BB/64, DD/64) = (32, 8) = 256 CTAs, 256 threads, occ 2 (all resident).
// ---------------------------------------------------------------------------
__global__ __launch_bounds__(256, 2)
void step_h(const float* __restrict__ feat, const float* __restrict__ Whh,
            const float* __restrict__ bhh, const float* __restrict__ bp,
            float* __restrict__ out, int t) {
    // Raw smem carved into phase-disjoint views:
    //   GEMM phase: As[2][16][68] float (8704 B) + Bs[2][3][16][68] float (26112 B)
    //   Proj phase: Hs[64][68] float (17408 B), overlapping As + head of Bs
    __shared__ __align__(16) unsigned char sraw[34816];
    float (*As)[16][68]    = (float(*)[16][68])sraw;
    float (*Bs)[3][16][68] = (float(*)[3][16][68])(sraw + 8704);
    float* Hs = (float*)sraw;  // stride 68

    const float* hin  = (t == 0) ? feat : g_h[(t - 1) & 1];
    float*       hout = g_h[t & 1];

    const int tid = threadIdx.x;
    const int m0 = blockIdx.x * 64, n0 = blockIdx.y * 64;
    // SWAPPED compute mapping: m-quad = tid&15 (streamed A), n-quad = tid>>4
    const int tq = tid & 15;   // m-quad: m = m0 + tq*4 + i
    const int nq = tid >> 4;   // n-quad: n = n0 + nq*4 + j
    const int sm = tid >> 2, skq = tid & 3;  // staging: row = tid/4, k-quad = tid%4

    // ---- Inline finalize of step t-1 (producer CTAs only) -----------------
    if (t > 0 && blockIdx.y == 0) {
        const int w = tid >> 5, lane = tid & 31;
        float* out_tok = out + (size_t)BB * CC * TT;
        const float4 bpv = *(const float4*)&bp[lane * 4];
        #pragma unroll
        for (int rr = 0; rr < 8; rr++) {
            const int b = m0 + w * 8 + rr;
            float4 s = make_float4(0.f, 0.f, 0.f, 0.f);
            #pragma unroll
            for (int p = 0; p < 8; p++) {
                float4 v = *(const float4*)&g_part[((size_t)p * BB + b) * CC + lane * 4];
                s.x += v.x; s.y += v.y; s.z += v.z; s.w += v.w;
            }
            s.x += bpv.x; s.y += bpv.y; s.z += bpv.z; s.w += bpv.w;

            *(float4*)&g_log[((size_t)b * TT + (t - 1)) * CC + lane * 4] = s;

            // argmax, first-max semantics
            float vv[4] = {s.x, s.y, s.z, s.w};
            float bv = -3.402823466e38f;
            int bi = 0;
            #pragma unroll
            for (int j = 0; j < 4; j++) {
                if (vv[j] > bv) { bv = vv[j]; bi = lane * 4 + j; }
            }
            #pragma unroll
            for (int off = 16; off; off >>= 1) {
                float ov = __shfl_xor_sync(0xffffffffu, bv, off);
                int   oi = __shfl_xor_sync(0xffffffffu, bi, off);
                if (ov > bv || (ov == bv && oi < bi)) { bv = ov; bi = oi; }
            }
            if (lane == 0) {
                g_tok[b] = bi;
                out_tok[(size_t)b * TT + (t - 1)] = (float)bi;
            }
        }
        __threadfence();
        __syncthreads();
        if (tid == 0) atomicExch(&g_done[blockIdx.x], t);
    }

    // ---- gh GEMM (bitwise-identical accumulation to R13) ------------------
    const float* pa  = hin + (size_t)(m0 + sm) * DD + skq * 4;
    const float* pb0 = Whh + (size_t)(n0 + sm) * DD + skq * 4;
    const float* pb1 = pb0 + (size_t)DD * DD;
    const float* pb2 = pb1 + (size_t)DD * DD;

    unsigned long long acc[3][4][2];
    #pragma unroll
    for (int g = 0; g < 3; g++)
        #pragma unroll
        for (int i = 0; i < 4; i++) { acc[g][i][0] = 0ull; acc[g][i][1] = 0ull; }

    float4 av, bv0, bv1, bv2;

    #define STORE_PANEL(s)                                                    \
        do {                                                                  \
            As[s][skq * 4 + 0][sm] = av.x;                                    \
            As[s][skq * 4 + 1][sm] = av.y;                                    \
            As[s][skq * 4 + 2][sm] = av.z;                                    \
            As[s][skq * 4 + 3][sm] = av.w;                                    \
            Bs[s][0][skq * 4 + 0][sm] = bv0.x; Bs[s][0][skq * 4 + 1][sm] = bv0.y; \
            Bs[s][0][skq * 4 + 2][sm] = bv0.z; Bs[s][0][skq * 4 + 3][sm] = bv0.w; \
            Bs[s][1][skq * 4 + 0][sm] = bv1.x; Bs[s][1][skq * 4 + 1][sm] = bv1.y; \
            Bs[s][1][skq * 4 + 2][sm] = bv1.z; Bs[s][1][skq * 4 + 3][sm] = bv1.w; \
            Bs[s][2][skq * 4 + 0][sm] = bv2.x; Bs[s][2][skq * 4 + 1][sm] = bv2.y; \
            Bs[s][2][skq * 4 + 2][sm] = bv2.z; Bs[s][2][skq * 4 + 3][sm] = bv2.w; \
        } while (0)

    // Prologue: panel 0 -> buf 0; panel 1 into regs.
    av  = *(const float4*)(pa);
    bv0 = *(const float4*)(pb0);
    bv1 = *(const float4*)(pb1);
    bv2 = *(const float4*)(pb2);
    STORE_PANEL(0);
    av  = *(const float4*)(pa  + 16);
    bv0 = *(const float4*)(pb0 + 16);
    bv1 = *(const float4*)(pb1 + 16);
    bv2 = *(const float4*)(pb2 + 16);
    __syncthreads();

    for (int p = 0; p < 32; p++) {
        const int s = p & 1;
        if (p < 31)
            STORE_PANEL(s ^ 1);
        if (p < 30) {
            const int kk = (p + 2) * 16;
            av  = *(const float4*)(pa  + kk);
            bv0 = *(const float4*)(pb0 + kk);
            bv1 = *(const float4*)(pb1 + kk);
            bv2 = *(const float4*)(pb2 + kk);
        }
        #pragma unroll
        for (int k = 0; k < 16; k++) {
            float4 a4 = *(const float4*)&As[s][k][tq * 4];              // 16 distinct/warp
            ulonglong2 br = *(const ulonglong2*)&Bs[s][0][k][nq * 4];   // 2 distinct/warp
            ulonglong2 bz = *(const ulonglong2*)&Bs[s][1][k][nq * 4];
            ulonglong2 bn = *(const ulonglong2*)&Bs[s][2][k][nq * 4];
            unsigned long long a[4] = {dup2(a4.x), dup2(a4.y), dup2(a4.z), dup2(a4.w)};
            #pragma unroll
            for (int i = 0; i < 4; i++) {
                FMA2(acc[0][i][0], a[i], br.x); FMA2(acc[0][i][1], a[i], br.y);
                FMA2(acc[1][i][0], a[i], bz.x); FMA2(acc[1][i][1], a[i], bz.y);
                FMA2(acc[2][i][0], a[i], bn.x); FMA2(acc[2][i][1], a[i], bn.y);
            }
        }
        __syncthreads();
    }
    #undef STORE_PANEL

    // ---- Wait for this m-block's tokens (set ~75us ago by the y==0 CTA) ---
    if (t > 0) {
        if (tid == 0) {
            while (((volatile int*)g_done)[blockIdx.x] < t) { }
        }
        __syncthreads();
        __threadfence();  // acquire: order g_tok reads after flag observation
    }

    // Gate epilogue: gi from table (b_ih + b_hh r/z folded in), b_hh_n added here.
    // Thread covers m = m0 + tq*4 + i, n = n0 + nq*4 + j.
    const float4 bhn4 = *(const float4*)&bhh[2 * DD + n0 + nq * 4];
    #pragma unroll
    for (int i = 0; i < 4; i++) {
        int m = m0 + tq * 4 + i;
        int tok = g_tok[m];
        const float* tab = g_tab + (size_t)tok * G3 + n0 + nq * 4;
        float4 gir  = *(const float4*)(tab);
        float4 giz  = *(const float4*)(tab + DD);
        float4 gin  = *(const float4*)(tab + 2 * DD);
        float4 hold = *(const float4*)&hin[(size_t)m * DD + n0 + nq * 4];

        float gr[4], gz[4], gn[4];
        gr[0] = lo32(acc[0][i][0]); gr[1] = hi32(acc[0][i][0]);
        gr[2] = lo32(acc[0][i][1]); gr[3] = hi32(acc[0][i][1]);
        gz[0] = lo32(acc[1][i][0]); gz[1] = hi32(acc[1][i][0]);
        gz[2] = lo32(acc[1][i][1]); gz[3] = hi32(acc[1][i][1]);
        gn[0] = lo32(acc[2][i][0]); gn[1] = hi32(acc[2][i][0]);
        gn[2] = lo32(acc[2][i][1]); gn[3] = hi32(acc[2][i][1]);

        float ir[4] = {gir.x, gir.y, gir.z, gir.w};
        float iz[4] = {giz.x, giz.y, giz.z, giz.w};
        float in_[4] = {gin.x, gin.y, gin.z, gin.w};
        float bn_[4] = {bhn4.x, bhn4.y, bhn4.z, bhn4.w};
        float ho[4] = {hold.x, hold.y, hold.z, hold.w};
        float o[4];
        #pragma unroll
        for (int j = 0; j < 4; j++) {
            float r = sigm(ir[j] + gr[j]);
            float z = sigm(iz[j] + gz[j]);
            float n = tanhf(in_[j] + r * (gn[j] + bn_[j]));
            o[j] = (1.f - z) * n + z * ho[j];
            Hs[(tq * 4 + i) * 68 + nq * 4 + j] = o[j];
        }
        *(float4*)&hout[(size_t)m * DD + n0 + nq * 4] =
            make_float4(o[0], o[1], o[2], o[3]);
    }
    __syncthreads();

    // Projection partial: P[m][c] = sum_{k=0..63} Hs[m][k] * WpT[n0+k][c]
    // Warp w owns rows w*8..w*8+7; lane owns 4 classes (c = lane*4..+3).
    {
        const int w = tid >> 5, lane = tid & 31;
        float4 pacc[8];
        #pragma unroll
        for (int rr = 0; rr < 8; rr++) pacc[rr] = make_float4(0.f, 0.f, 0.f, 0.f);

        #pragma unroll 4
        for (int kq = 0; kq < 16; kq++) {
            const float* wr = g_wpt + (size_t)(n0 + kq * 4) * CC + lane * 4;
            float4 w0 = *(const float4*)(wr);
            float4 w1 = *(const float4*)(wr + CC);
            float4 w2 = *(const float4*)(wr + 2 * CC);
            float4 w3 = *(const float4*)(wr + 3 * CC);
            #pragma unroll
            for (int rr = 0; rr < 8; rr++) {
                float4 a4 = *(const float4*)&Hs[(w * 8 + rr) * 68 + kq * 4];
                pacc[rr].x += a4.x * w0.x; pacc[rr].y += a4.x * w0.y;
                pacc[rr].z += a4.x * w0.z; pacc[rr].w += a4.x * w0.w;
                pacc[rr].x += a4.y * w1.x; pacc[rr].y += a4.y * w1.y;
                pacc[rr].z += a4.y * w1.z; pacc[rr].w += a4.y * w1.w;
                pacc[rr].x += a4.z * w2.x; pacc[rr].y += a4.z * w2.y;
                pacc[rr].z += a4.z * w2.z; pacc[rr].w += a4.z * w2.w;
                pacc[rr].x += a4.w * w3.x; pacc[rr].y += a4.w * w3.y;
                pacc[rr].z += a4.w * w3.z; pacc[rr].w += a4.w * w3.w;
            }
        }
        const int nt = blockIdx.y;
        #pragma unroll
        for (int rr = 0; rr < 8; rr++) {
            int b = m0 + w * 8 + rr;
            *(float4*)&g_part[((size_t)nt * BB + b) * CC + lane * 4] = pacc[rr];
        }
    }
}

// ---------------------------------------------------------------------------
// Kernel 2 (once, after the loop): finalize step TT-1.
// grid 256 CTAs x 256 threads; one warp per batch row.
// ---------------------------------------------------------------------------
__global__ __launch_bounds__(256)
void finalize(const float* __restrict__ bp, float* __restrict__ out, int t) {
    const int tid = threadIdx.x;
    const int w = tid >> 5, lane = tid & 31;
    const int b = blockIdx.x * 8 + w;

    float4 s = make_float4(0.f, 0.f, 0.f, 0.f);
    #pragma unroll
    for (int p = 0; p < 8; p++) {
        float4 v = *(const float4*)&g_part[((size_t)p * BB + b) * CC + lane * 4];
        s.x += v.x; s.y += v.y; s.z += v.z; s.w += v.w;
    }
    const float4 bpv = *(const float4*)&bp[lane * 4];
    s.x += bpv.x; s.y += bpv.y; s.z += bpv.z; s.w += bpv.w;

    *(float4*)&g_log[((size_t)b * TT + t) * CC + lane * 4] = s;

    // argmax, first-max semantics
    float vv[4] = {s.x, s.y, s.z, s.w};
    float bv = -3.402823466e38f;
    int bi = 0;
    #pragma unroll
    for (int j = 0; j < 4; j++) {
        if (vv[j] > bv) { bv = vv[j]; bi = lane * 4 + j; }
    }
    #pragma unroll
    for (int off = 16; off; off >>= 1) {
        float ov = __shfl_xor_sync(0xffffffffu, bv, off);
        int   oi = __shfl_xor_sync(0xffffffffu, bi, off);
        if (ov > bv || (ov == bv && oi < bi)) { bv = ov; bi = oi; }
    }
    if (lane == 0) {
        g_tok[b] = bi;
        float* out_tok = out + (size_t)BB * CC * TT;
        out_tok[(size_t)b * TT + t] = (float)bi;
    }
}

// ---------------------------------------------------------------------------
// Kernel 3 (once, at end): transpose staged logits [B,T,C] -> d_out [B,C,T].
// ---------------------------------------------------------------------------
__global__ __launch_bounds__(256)
void transp(float* __restrict__ out) {
    __shared__ float tile[32][33];
    const int b  = blockIdx.z;
    const int t0 = blockIdx.x * 32, c0 = blockIdx.y * 32;
    const int tx = threadIdx.x, ty = threadIdx.y;

    #pragma unroll
    for (int i = ty; i < 32; i += 8) {
        int t = t0 + i;
        if (t < TT)
            tile[i][tx] = g_log[((size_t)b * TT + t) * CC + c0 + tx];
    }
    __syncthreads();
    #pragma unroll
    for (int i = ty; i < 32; i += 8) {
        int c = c0 + i;
        int t = t0 + tx;
        if (t < TT)
            out[((size_t)b * CC + c) * TT + t] = tile[tx][i];
    }
}

// ---------------------------------------------------------------------------
// kernel_launch: graph-capturable, no allocation.
// Inputs (metadata order): feat, W_ih, W_hh, b_ih, b_hh, W_proj, b_proj, embed
// Output: logits [B,C,T] float32 then tokens [B,T] as float32.
// ---------------------------------------------------------------------------
extern "C" void kernel_launch(void* const* d_in, const int* in_sizes, int n_in,
                              void* d_out, int out_size) {
    const float* feat  = (const float*)d_in[0];
    const float* Wih   = (const float*)d_in[1];
    const float* Whh   = (const float*)d_in[2];
    const float* bih   = (const float*)d_in[3];
    const float* bhh   = (const float*)d_in[4];
    const float* Wp    = (const float*)d_in[5];
    const float* bp    = (const float*)d_in[6];
    const float* embed = (const float*)d_in[7];
    float* out = (float*)d_out;

    build_tab<<<dim3(CC + 1, G3 / 256), 256>>>(Wih, bih, bhh, embed);
    build_wpt<<<DD * CC / 256, 256>>>(Wp);
    init_tok<<<(BB + 255) / 256, 256>>>();

    for (int t = 0; t < TT; t++) {
        step_h<<<dim3(BB / 64, DD / 64), 256>>>(feat, Whh, bhh, bp, out, t);
    }
    finalize<<<BB / 8, 256>>>(bp, out, TT - 1);

    transp<<<dim3((TT + 31) / 32, CC / 32, BB), dim3(32, 8)>>>(out);
}